// round 6
// baseline (speedup 1.0000x reference)
#include <cuda_runtime.h>
#include <cuda_fp16.h>

#define BATCH 64
#define NIN   2048
#define DIN   16
#define NOUT  32
#define DOUT  32
#define JD    (NOUT*DOUT)   // 1024
#define XSTR  68            // padded row stride for transposed x staging

// Scratch (device globals — no allocation allowed)
__device__ __half2 g_uhat[(size_t)BATCH * NIN * (JD/2)];  // [b][i][jd/2], 268 MB
__device__ float   g_s[BATCH * JD];
__device__ float   g_vsum[BATCH * JD];
__device__ int     g_cnt[3 * BATCH];    // completion counters (R0, route1, route2)

// ---------- packed f32x2 helpers (sm_103a) ----------
__device__ __forceinline__ unsigned long long pack2(float lo, float hi) {
    unsigned long long r;
    asm("mov.b64 %0, {%1, %2};" : "=l"(r) : "f"(lo), "f"(hi));
    return r;
}
__device__ __forceinline__ void unpack2(unsigned long long v, float& lo, float& hi) {
    asm("mov.b64 {%0, %1}, %2;" : "=f"(lo), "=f"(hi) : "l"(v));
}
__device__ __forceinline__ unsigned long long ffma2(unsigned long long a,
                                                    unsigned long long b,
                                                    unsigned long long c) {
    unsigned long long d;
    asm("fma.rn.f32x2 %0, %1, %2, %3;" : "=l"(d) : "l"(a), "l"(b), "l"(c));
    return d;
}
__device__ __forceinline__ unsigned long long fadd2(unsigned long long a,
                                                    unsigned long long b) {
    unsigned long long d;
    asm("add.rn.f32x2 %0, %1, %2;" : "=l"(d) : "l"(a), "l"(b));
    return d;
}

__global__ void kernelZero() {
    int t = blockIdx.x * 1024 + threadIdx.x;
    g_s[t] = 0.f;
    g_vsum[t] = 0.f;
    if (blockIdx.x == 0 && threadIdx.x < 3 * BATCH) g_cnt[threadIdx.x] = 0;
}

// Squash for one batch b, executed by the LAST finishing block of a producer
// kernel (threadfence-reduction). nthr = blockDim (multiple of 32 so each
// warp covers one j per pass). Reads g_s via .cg, computes v, accumulates
// g_vsum, zeroes g_s, optionally writes vout.
__device__ __forceinline__ void squashTail(int b, float pre, int nthr,
                                           float* vout, bool writeOut) {
    for (int r = threadIdx.x; r < JD; r += nthr) {
        float s = __ldcg(&g_s[b * JD + r]) * pre;
        float s2 = s * s;
#pragma unroll
        for (int off = 16; off; off >>= 1) s2 += __shfl_xor_sync(0xffffffffu, s2, off);
        float scale = (s2 / (1.f + s2 + 1e-9f)) * rsqrtf(s2 + 1e-9f);
        float v = s * scale;
        if (writeOut) vout[b * JD + r] = v;
        g_vsum[b * JD + r] += v;
        g_s[b * JD + r] = 0.f;
    }
}

// u_hat[b,i,jd] = sum_k W[i,jd,k] * x[b,i,k]; store fp16.
// One block per i. Thread t owns jd pair (2t, 2t+1). x staged TRANSPOSED
// (xs[k][b], stride 68): a broadcast LDS.128 over a b-quad yields {x_b0,x_b1}
// and {x_b2,x_b3} already packed for fma.rn.f32x2 — no per-iteration movs.
__global__ void __launch_bounds__(512) kernelU(const float* __restrict__ x,
                                               const float* __restrict__ W) {
    __shared__ __align__(16) float xs[DIN * XSTR];   // 4.3 KB
    const int i = blockIdx.x;
    const int t = threadIdx.x;

    // stage x[:, i, :] transposed: xs[k*XSTR + b]
    {
        int r0 = t, r1 = t + 512;
        int b0 = r0 >> 4, k0 = r0 & 15;
        int b1 = r1 >> 4, k1 = r1 & 15;
        float v0 = x[(size_t)b0 * (NIN * DIN) + (size_t)i * DIN + k0];
        float v1 = x[(size_t)b1 * (NIN * DIN) + (size_t)i * DIN + k1];
        xs[k0 * XSTR + b0] = v0;
        xs[k1 * XSTR + b1] = v1;
    }

    // W rows for jd0 = 2t, jd1 = 2t+1, each element duplicated {w,w}
    const float4* W4 = reinterpret_cast<const float4*>(W + (size_t)i * JD * DIN);
    unsigned long long wd0[DIN], wd1[DIN];
#pragma unroll
    for (int q = 0; q < 4; q++) {
        float4 fa = W4[8 * t + q];
        float4 fb = W4[8 * t + 4 + q];
        wd0[4*q+0] = pack2(fa.x, fa.x); wd0[4*q+1] = pack2(fa.y, fa.y);
        wd0[4*q+2] = pack2(fa.z, fa.z); wd0[4*q+3] = pack2(fa.w, fa.w);
        wd1[4*q+0] = pack2(fb.x, fb.x); wd1[4*q+1] = pack2(fb.y, fb.y);
        wd1[4*q+2] = pack2(fb.z, fb.z); wd1[4*q+3] = pack2(fb.w, fb.w);
    }
    __syncthreads();

    __half2* outp = g_uhat + (size_t)i * (JD/2) + t;
    const size_t bstr = (size_t)NIN * (JD/2);

#pragma unroll 1
    for (int p = 0; p < BATCH / 4; p++) {      // b-quad
        unsigned long long a01_0 = 0ull, a23_0 = 0ull;
        unsigned long long a01_1 = 0ull, a23_1 = 0ull;
#pragma unroll
        for (int k = 0; k < DIN; k++) {
            ulonglong2 xp = *reinterpret_cast<const ulonglong2*>(&xs[k * XSTR + 4 * p]);
            a01_0 = ffma2(wd0[k], xp.x, a01_0);
            a23_0 = ffma2(wd0[k], xp.y, a23_0);
            a01_1 = ffma2(wd1[k], xp.x, a01_1);
            a23_1 = ffma2(wd1[k], xp.y, a23_1);
        }
        float f00, f10, f01, f11, f20, f30, f21, f31;
        unpack2(a01_0, f00, f10);   // jd0 for b0,b1
        unpack2(a01_1, f01, f11);   // jd1 for b0,b1
        unpack2(a23_0, f20, f30);   // jd0 for b2,b3
        unpack2(a23_1, f21, f31);   // jd1 for b2,b3
        outp[(size_t)(4*p + 0) * bstr] = __floats2half2_rn(f00, f01);
        outp[(size_t)(4*p + 1) * bstr] = __floats2half2_rn(f10, f11);
        outp[(size_t)(4*p + 2) * bstr] = __floats2half2_rn(f20, f21);
        outp[(size_t)(4*p + 3) * bstr] = __floats2half2_rn(f30, f31);
    }
}

// Iter-0: s0[b,jd] = sum_i u_hat[b,i,jd]; last block per b also squashes
// (uniform c folded in via pre=1/32).
__global__ void __launch_bounds__(256) kernelR0() {
    const int b = blockIdx.x;
    const int chunk = blockIdx.y;         // 16 chunks of 128 i's
    const int t = threadIdx.x;            // owns half2 pair -> jd 4t..4t+3
    float a0 = 0.f, a1 = 0.f, a2 = 0.f, a3 = 0.f;
    const uint2* base = reinterpret_cast<const uint2*>(
        g_uhat + ((size_t)b * NIN + (size_t)chunk * 128) * (JD/2)) + t;
#pragma unroll 4
    for (int ii = 0; ii < 128; ii++) {
        uint2 u = base[(size_t)ii * 256];
        float2 f0 = __half22float2(*reinterpret_cast<__half2*>(&u.x));
        float2 f1 = __half22float2(*reinterpret_cast<__half2*>(&u.y));
        a0 += f0.x; a1 += f0.y; a2 += f1.x; a3 += f1.y;
    }
    atomicAdd(&g_s[b * JD + 4*t + 0], a0);
    atomicAdd(&g_s[b * JD + 4*t + 1], a1);
    atomicAdd(&g_s[b * JD + 4*t + 2], a2);
    atomicAdd(&g_s[b * JD + 4*t + 3], a3);

    // threadfence-reduction tail: every thread fences its own atomics, the
    // block barrier makes them all precede the counter increment.
    __threadfence();
    __syncthreads();
    __shared__ int done;
    if (t == 0) done = atomicAdd(&g_cnt[0 * BATCH + b], 1);
    __syncthreads();
    if (done == 15) {
        __threadfence();
        squashTail(b, 1.f / 32.f, 256, nullptr, false);
    }
}

// Routing iter (k>=1), warp-local: lane = output capsule j. Last chunk-block
// per b runs the squash (and for the final iter writes d_out).
__global__ void __launch_bounds__(128) kernelRoute(int cntRow,
                                                   float* __restrict__ vout,
                                                   int writeOut) {
    const int b = blockIdx.x;
    const int chunk = blockIdx.y;         // 16 chunks of 128 i's
    const int w = threadIdx.x >> 5;       // warp 0..3
    const int j = threadIdx.x & 31;       // lane = output capsule

    __shared__ float sred[4][JD];         // 16 KB per-warp partials

    // vsum row for capsule j, packed f32x2
    unsigned long long v2[16];
    {
        const float4* vp = reinterpret_cast<const float4*>(g_vsum + b * JD + j * DOUT);
#pragma unroll
        for (int q = 0; q < 8; q++) {
            float4 f = vp[q];
            v2[2*q]   = pack2(f.x, f.y);
            v2[2*q+1] = pack2(f.z, f.w);
        }
    }

    unsigned long long acc2[16];
#pragma unroll
    for (int q = 0; q < 16; q++) acc2[q] = 0ull;

    const int i0 = chunk * 128 + w * 32;
    for (int ii = 0; ii < 32; ii++) {
        const uint4* up = reinterpret_cast<const uint4*>(
            g_uhat + ((size_t)b * NIN + i0 + ii) * (JD/2));
        uint4 qq[4];
        qq[0] = up[j*4 + 0];
        qq[1] = up[j*4 + 1];
        qq[2] = up[j*4 + 2];
        qq[3] = up[j*4 + 3];

        unsigned long long u2[16];
#pragma unroll
        for (int q = 0; q < 4; q++) {
            const unsigned int* rr = &qq[q].x;
#pragma unroll
            for (int r = 0; r < 4; r++) {
                float2 f = __half22float2(*reinterpret_cast<const __half2*>(&rr[r]));
                u2[4*q + r] = pack2(f.x, f.y);
            }
        }

        unsigned long long lA = 0ull, lB = 0ull;
#pragma unroll
        for (int q = 0; q < 8; q++) {
            lA = ffma2(u2[2*q],   v2[2*q],   lA);
            lB = ffma2(u2[2*q+1], v2[2*q+1], lB);
        }
        float l0, l1;
        unpack2(fadd2(lA, lB), l0, l1);
        float l = l0 + l1;

        float m = l;
#pragma unroll
        for (int off = 16; off; off >>= 1) m = fmaxf(m, __shfl_xor_sync(0xffffffffu, m, off));
        float e = __expf(l - m);
        float se = e;
#pragma unroll
        for (int off = 16; off; off >>= 1) se += __shfl_xor_sync(0xffffffffu, se, off);
        float c = e / se;
        unsigned long long c2 = pack2(c, c);

#pragma unroll
        for (int q = 0; q < 16; q++) acc2[q] = ffma2(u2[q], c2, acc2[q]);
    }

    // per-warp partials, xor-swizzled conflict-free
#pragma unroll
    for (int q = 0; q < 16; q++) {
        float a0, a1;
        unpack2(acc2[q], a0, a1);
        sred[w][j * DOUT + ((2*q)     ^ j)] = a0;
        sred[w][j * DOUT + ((2*q + 1) ^ j)] = a1;
    }
    __syncthreads();

    for (int r = threadIdx.x; r < JD; r += 128) {
        int jj = r >> 5, dd = r & 31;
        int d = dd ^ jj;
        float sum = sred[0][r] + sred[1][r] + sred[2][r] + sred[3][r];
        atomicAdd(&g_s[b * JD + jj * DOUT + d], sum);
    }

    // threadfence-reduction tail (fence -> barrier -> increment)
    __threadfence();
    __syncthreads();
    __shared__ int done;
    if (threadIdx.x == 0) done = atomicAdd(&g_cnt[cntRow * BATCH + b], 1);
    __syncthreads();
    if (done == 15) {
        __threadfence();
        squashTail(b, 1.f, 128, vout, writeOut != 0);
    }
}

extern "C" void kernel_launch(void* const* d_in, const int* in_sizes, int n_in,
                              void* d_out, int out_size) {
    const float* x = (const float*)d_in[0];   // [64, 2048, 16]
    const float* W = (const float*)d_in[1];   // [1, 2048, 32, 32, 16]
    float* out = (float*)d_out;               // [64, 32, 32]

    kernelZero<<<64, 1024>>>();
    kernelU<<<2048, 512>>>(x, W);
    kernelR0<<<dim3(64, 16), 256>>>();                 // + squash iter 0
    kernelRoute<<<dim3(64, 16), 128>>>(1, out, 0);     // + squash iter 1
    kernelRoute<<<dim3(64, 16), 128>>>(2, out, 1);     // + squash iter 2 -> d_out
}

// round 8
// speedup vs baseline: 1.0760x; 1.0760x over previous
#include <cuda_runtime.h>
#include <cuda_fp16.h>

#define BATCH 64
#define NIN   2048
#define DIN   16
#define NOUT  32
#define DOUT  32
#define JD    (NOUT*DOUT)   // 1024

// Scratch (device globals — no allocation allowed)
__device__ __half2 g_uhat[(size_t)BATCH * NIN * (JD/2)];  // [b][i][jd/2], 268 MB
__device__ float   g_s[BATCH * JD];
__device__ float   g_vsum[BATCH * JD];
__device__ int     g_cnt[3 * BATCH];    // completion counters (R0, route1, route2)

// ---------- packed f32x2 helpers (sm_103a) ----------
__device__ __forceinline__ unsigned long long pack2(float lo, float hi) {
    unsigned long long r;
    asm("mov.b64 %0, {%1, %2};" : "=l"(r) : "f"(lo), "f"(hi));
    return r;
}
__device__ __forceinline__ void unpack2(unsigned long long v, float& lo, float& hi) {
    asm("mov.b64 {%0, %1}, %2;" : "=f"(lo), "=f"(hi) : "l"(v));
}
__device__ __forceinline__ unsigned long long ffma2(unsigned long long a,
                                                    unsigned long long b,
                                                    unsigned long long c) {
    unsigned long long d;
    asm("fma.rn.f32x2 %0, %1, %2, %3;" : "=l"(d) : "l"(a), "l"(b), "l"(c));
    return d;
}
__device__ __forceinline__ unsigned long long fadd2(unsigned long long a,
                                                    unsigned long long b) {
    unsigned long long d;
    asm("add.rn.f32x2 %0, %1, %2;" : "=l"(d) : "l"(a), "l"(b));
    return d;
}

// Squash for one batch b, executed by the LAST finishing block of a producer
// kernel. Reads g_s via .cg, computes v, accumulates g_vsum, zeroes g_s,
// optionally writes vout. Each warp pass covers exactly one j (32 d's).
__device__ __forceinline__ void squashTail(int b, float pre, int nthr,
                                           float* vout, bool writeOut) {
    for (int r = threadIdx.x; r < JD; r += nthr) {
        float s = __ldcg(&g_s[b * JD + r]) * pre;
        float s2 = s * s;
#pragma unroll
        for (int off = 16; off; off >>= 1) s2 += __shfl_xor_sync(0xffffffffu, s2, off);
        float scale = (s2 / (1.f + s2 + 1e-9f)) * rsqrtf(s2 + 1e-9f);
        float v = s * scale;
        if (writeOut) vout[b * JD + r] = v;
        g_vsum[b * JD + r] += v;
        g_s[b * JD + r] = 0.f;
    }
}

// u_hat[b,i,jd] = sum_k W[i,jd,k] * x[b,i,k]; store fp16.
// One block per i. Thread t owns jd pair (2t, 2t+1); W rows packed {w0,w1}
// per k. x staged as plain float4, read with warp-broadcast LDS.128.
// Also fuses the scratch zeroing (blocks 0..64) — replaces kernelZero.
__global__ void __launch_bounds__(512) kernelU(const float* __restrict__ x,
                                               const float* __restrict__ W) {
    __shared__ float4 xs[BATCH * 4];     // [b][quarter], 4 KB
    const int i = blockIdx.x;
    const int t = threadIdx.x;

    // fused zeroing (independent of this block's compute)
    if (i < BATCH) {
        g_s[i * JD + t]       = 0.f;
        g_s[i * JD + 512 + t] = 0.f;
        g_vsum[i * JD + t]       = 0.f;
        g_vsum[i * JD + 512 + t] = 0.f;
    } else if (i == BATCH && t < 3 * BATCH) {
        g_cnt[t] = 0;
    }

    if (t < BATCH * 4) {
        int b = t >> 2, q = t & 3;
        xs[t] = reinterpret_cast<const float4*>(
                    x + (size_t)b * (NIN * DIN) + (size_t)i * DIN)[q];
    }

    // W rows for jd0 = 2t, jd1 = 2t+1 (16 floats each), packed per-k
    const float4* W4 = reinterpret_cast<const float4*>(W + (size_t)i * JD * DIN);
    float4 wa[4], wb[4];
#pragma unroll
    for (int q = 0; q < 4; q++) { wa[q] = W4[8 * t + q]; wb[q] = W4[8 * t + 4 + q]; }
    unsigned long long w2[DIN];
#pragma unroll
    for (int q = 0; q < 4; q++) {
        const float* pa = &wa[q].x;
        const float* pb = &wb[q].x;
#pragma unroll
        for (int r = 0; r < 4; r++) w2[4*q + r] = pack2(pa[r], pb[r]);
    }
    __syncthreads();

    __half2* outp = g_uhat + (size_t)i * (JD/2) + t;
#pragma unroll 2
    for (int b = 0; b < BATCH; b++) {
        const float4* xb = xs + b * 4;
        unsigned long long accA = 0ull, accB = 0ull;
#pragma unroll
        for (int q = 0; q < 4; q++) {
            float4 f = xb[q];             // broadcast LDS.128
            accA = ffma2(w2[4*q + 0], pack2(f.x, f.x), accA);
            accB = ffma2(w2[4*q + 1], pack2(f.y, f.y), accB);
            accA = ffma2(w2[4*q + 2], pack2(f.z, f.z), accA);
            accB = ffma2(w2[4*q + 3], pack2(f.w, f.w), accB);
        }
        unsigned long long acc = fadd2(accA, accB);
        float a0, a1;
        unpack2(acc, a0, a1);
        outp[(size_t)b * NIN * (JD/2)] = __floats2half2_rn(a0, a1);
    }
}

// Iter-0: s0[b,jd] = sum_i u_hat[b,i,jd]; last block per b also squashes
// (uniform c folded in via pre=1/32).
__global__ void __launch_bounds__(256) kernelR0() {
    const int b = blockIdx.x;
    const int chunk = blockIdx.y;         // 16 chunks of 128 i's
    const int t = threadIdx.x;            // owns half2 pair -> jd 4t..4t+3
    float a0 = 0.f, a1 = 0.f, a2 = 0.f, a3 = 0.f;
    const uint2* base = reinterpret_cast<const uint2*>(
        g_uhat + ((size_t)b * NIN + (size_t)chunk * 128) * (JD/2)) + t;
#pragma unroll 8
    for (int ii = 0; ii < 128; ii++) {
        uint2 u = __ldcg(base + (size_t)ii * 256);   // 256 uint2 = 512 half2 = one row
        float2 f0 = __half22float2(*reinterpret_cast<__half2*>(&u.x));
        float2 f1 = __half22float2(*reinterpret_cast<__half2*>(&u.y));
        a0 += f0.x; a1 += f0.y; a2 += f1.x; a3 += f1.y;
    }
    atomicAdd(&g_s[b * JD + 4*t + 0], a0);
    atomicAdd(&g_s[b * JD + 4*t + 1], a1);
    atomicAdd(&g_s[b * JD + 4*t + 2], a2);
    atomicAdd(&g_s[b * JD + 4*t + 3], a3);

    // threadfence-reduction tail (fence -> barrier -> increment)
    __threadfence();
    __syncthreads();
    __shared__ int done;
    if (t == 0) done = atomicAdd(&g_cnt[0 * BATCH + b], 1);
    __syncthreads();
    if (done == 15) {
        __threadfence();
        squashTail(b, 1.f / 32.f, 256, nullptr, false);
    }
}

// Routing iter (k>=1), warp-local: lane = output capsule j.
// Scalar math (low reg pressure), software prefetch of next i's 4x uint4,
// softmax WITHOUT max-subtraction (logits provably small: |vsum|<=2, so
// |l| <~ 10 and bare __expf is exact-equivalent). Zero block barriers in
// the loop; warp->block reduction via xor-swizzled STS, then atomics.
// NOTE: one u_hat row = 512 half2 = 128 uint4  -> per-i stride is 128 uint4.
__global__ void __launch_bounds__(128) kernelRoute(int cntRow,
                                                   float* __restrict__ vout,
                                                   int writeOut) {
    const int b = blockIdx.x;
    const int chunk = blockIdx.y;         // 16 chunks of 128 i's
    const int w = threadIdx.x >> 5;       // warp 0..3
    const int j = threadIdx.x & 31;       // lane = output capsule

    __shared__ float sred[4][JD];         // 16 KB per-warp partials

    float v[DOUT];
    {
        const float4* vp = reinterpret_cast<const float4*>(g_vsum + b * JD + j * DOUT);
#pragma unroll
        for (int q = 0; q < 8; q++) {
            float4 f = vp[q];
            v[4*q+0] = f.x; v[4*q+1] = f.y; v[4*q+2] = f.z; v[4*q+3] = f.w;
        }
    }

    float acc[DOUT];
#pragma unroll
    for (int d = 0; d < DOUT; d++) acc[d] = 0.f;

    const uint4* up = reinterpret_cast<const uint4*>(
        g_uhat + ((size_t)b * NIN + chunk * 128 + w * 32) * (JD/2)) + j * 4;

    uint4 cur[4];
#pragma unroll
    for (int q = 0; q < 4; q++) cur[q] = __ldcg(up + q);

#pragma unroll 1
    for (int ii = 0; ii < 32; ii++) {
        uint4 nxt[4];
        if (ii < 31) {
            const uint4* np = up + (size_t)(ii + 1) * 128;   // 128 uint4 per row
#pragma unroll
            for (int q = 0; q < 4; q++) nxt[q] = __ldcg(np + q);
        } else {
#pragma unroll
            for (int q = 0; q < 4; q++) nxt[q] = cur[q];
        }

        // logit = u . v (two chains), converting from raw half2 words
        float lA = 0.f, lB = 0.f;
#pragma unroll
        for (int q = 0; q < 4; q++) {
            const unsigned int* ww = &cur[q].x;
#pragma unroll
            for (int r = 0; r < 4; r++) {
                float2 f = __half22float2(*reinterpret_cast<const __half2*>(&ww[r]));
                int d = q * 8 + r * 2;
                lA = fmaf(f.x, v[d],     lA);
                lB = fmaf(f.y, v[d + 1], lB);
            }
        }
        float l = lA + lB;

        // warp softmax over j (no max-subtraction needed)
        float e = __expf(l);
        float se = e;
#pragma unroll
        for (int off = 16; off; off >>= 1) se += __shfl_xor_sync(0xffffffffu, se, off);
        float cc = __fdividef(e, se);

        // weighted accumulate (re-convert; saves 32 live registers)
#pragma unroll
        for (int q = 0; q < 4; q++) {
            const unsigned int* ww = &cur[q].x;
#pragma unroll
            for (int r = 0; r < 4; r++) {
                float2 f = __half22float2(*reinterpret_cast<const __half2*>(&ww[r]));
                int d = q * 8 + r * 2;
                acc[d]     = fmaf(cc, f.x, acc[d]);
                acc[d + 1] = fmaf(cc, f.y, acc[d + 1]);
            }
        }
#pragma unroll
        for (int q = 0; q < 4; q++) cur[q] = nxt[q];
    }

    // per-warp partials, xor-swizzled conflict-free
#pragma unroll
    for (int d = 0; d < DOUT; d++) sred[w][j * DOUT + (d ^ j)] = acc[d];
    __syncthreads();

    for (int r = threadIdx.x; r < JD; r += 128) {
        int jj = r >> 5, dd = r & 31;
        int d = dd ^ jj;
        float sum = sred[0][r] + sred[1][r] + sred[2][r] + sred[3][r];
        atomicAdd(&g_s[b * JD + jj * DOUT + d], sum);
    }

    // threadfence-reduction tail (fence -> barrier -> increment)
    __threadfence();
    __syncthreads();
    __shared__ int done;
    if (threadIdx.x == 0) done = atomicAdd(&g_cnt[cntRow * BATCH + b], 1);
    __syncthreads();
    if (done == 15) {
        __threadfence();
        squashTail(b, 1.f, 128, vout, writeOut != 0);
    }
}

extern "C" void kernel_launch(void* const* d_in, const int* in_sizes, int n_in,
                              void* d_out, int out_size) {
    const float* x = (const float*)d_in[0];   // [64, 2048, 16]
    const float* W = (const float*)d_in[1];   // [1, 2048, 32, 32, 16]
    float* out = (float*)d_out;               // [64, 32, 32]

    kernelU<<<2048, 512>>>(x, W);                      // + fused zeroing
    kernelR0<<<dim3(64, 16), 256>>>();                 // + squash iter 0
    kernelRoute<<<dim3(64, 16), 128>>>(1, out, 0);     // + squash iter 1
    kernelRoute<<<dim3(64, 16), 128>>>(2, out, 1);     // + squash iter 2 -> d_out
}